// round 15
// baseline (speedup 1.0000x reference)
#include <cuda_runtime.h>
#include <cuda_fp16.h>
#include <math.h>
#include <stdint.h>

// ---------------------------------------------------------------------------
// SwinBlock, GEMMs on HMMA mma.sync m16n8k16 fp16 (fp32 acc).
// NEW: whole layer executed in 4 batch-chunks (8 images each) so every
// intermediate tensor (qkv 58MB, hidden 77MB, x1 38MB, a16 19MB) stays
// L2-resident and chunk buffers are reused -> ~1.2GB less DRAM traffic.
// Shapes fixed: B=32, H=W=56, C=384, NH=12, hd=32, WS=7, SHIFT=3, HID=1536
// ---------------------------------------------------------------------------

#define NTOK   100352          // 2048 windows * 49 tokens
#define NCHUNK 4
#define CHTOK  25088           // tokens per chunk (8 images, 512 windows)
#define CHWIN  512
#define CDIM   384
#define NHEAD  12
#define HD     32
#define N3     1152
#define HIDD   1536
#define FULLMASK 0xffffffffu

// GEMM tiling: CTA 128x128, BK=64, 2-stage cp.async pipeline, 128 threads
#define BK       64
#define ROWB     144                       // 64 fp16 = 128B, padded to 144B
#define TBYTES   (128 * ROWB)              // 18432 per tensor tile
#define STAGEB   (2 * TBYTES)              // A tile + B tile = 36864
#define NSTAGE   2
#define SMEM_TOTAL (NSTAGE * STAGEB)       // 73728 B dynamic smem

// ---------------- scratch (static device globals; chunk-sized, reused) -----
__device__ __half  g_qkv16[(size_t)CHTOK * N3];   // fp16 qkv      (58 MB)
__device__ float   g_x1 [(size_t)CHTOK * CDIM];   // residual      (38 MB)
__device__ __half  g_a  [(size_t)CHTOK * CDIM];   // activations   (19 MB)
__device__ __half  g_h  [(size_t)CHTOK * HIDD];   // MLP hidden    (77 MB)
// transposed fp16 weights: Wt[N][K]
__device__ __half  g_wqkv[N3  * CDIM];
__device__ __half  g_wprj[CDIM* CDIM];
__device__ __half  g_wfc1[HIDD* CDIM];
__device__ __half  g_wfc2[CDIM* HIDD];

// ---------------- PTX helpers ----------------------------------------------
__device__ __forceinline__ uint32_t smem_u32(const void* p) {
    uint32_t a;
    asm("{ .reg .u64 t; cvta.to.shared.u64 t, %1; cvt.u32.u64 %0, t; }"
        : "=r"(a) : "l"(p));
    return a;
}
__device__ __forceinline__ void ldm_x4(uint32_t* r, uint32_t a) {
    asm volatile("ldmatrix.sync.aligned.m8n8.x4.shared.b16 {%0,%1,%2,%3}, [%4];"
                 : "=r"(r[0]), "=r"(r[1]), "=r"(r[2]), "=r"(r[3]) : "r"(a));
}
__device__ __forceinline__ void mma_f16(float* c, const uint32_t* a,
                                        uint32_t b0, uint32_t b1) {
    asm volatile("mma.sync.aligned.m16n8k16.row.col.f32.f16.f16.f32 "
                 "{%0,%1,%2,%3}, {%4,%5,%6,%7}, {%8,%9}, {%0,%1,%2,%3};"
                 : "+f"(c[0]), "+f"(c[1]), "+f"(c[2]), "+f"(c[3])
                 : "r"(a[0]), "r"(a[1]), "r"(a[2]), "r"(a[3]), "r"(b0), "r"(b1));
}
__device__ __forceinline__ void cp16(uint32_t sa, const void* ga) {
    asm volatile("cp.async.cg.shared.global [%0], [%1], 16;" :: "r"(sa), "l"(ga));
}
#define CP_COMMIT()  asm volatile("cp.async.commit_group;")
#define CP_WAIT(n)   asm volatile("cp.async.wait_group %0;" :: "n"(n))

// ---------------- weight transpose to fp16: W[K][N] -> Wt[N][K] -------------
__global__ void wT(const float* __restrict__ W, __half* __restrict__ o, int K, int N)
{
    int idx = blockIdx.x * 256 + threadIdx.x;
    if (idx >= K * N) return;
    int n = idx / K, k = idx - n * K;
    o[idx] = __float2half_rn(W[(size_t)k * N + n]);
}

// ---------------- LayerNorm (optionally fused roll + window partition) -----
// Chunk-local: x points at the chunk's first image; out rows are chunk-local.
template<bool WINDOW>
__global__ __launch_bounds__(128)
void ln_kernel(const float* __restrict__ x, const float* __restrict__ g,
               const float* __restrict__ bta, __half* __restrict__ o)
{
    __shared__ float sa[4], sb[4];
    const int token = blockIdx.x;
    size_t src;
    if (WINDOW) {
        int bwin  = token / 49;
        int n     = token - bwin * 49;
        int batch = bwin >> 6;          // chunk-local batch 0..7
        int widx  = bwin & 63;
        int wh = widx >> 3, ww = widx & 7;
        int r = n / 7, c = n - r * 7;
        int fr = wh * 7 + r + 3; if (fr >= 56) fr -= 56;
        int fc = ww * 7 + c + 3; if (fc >= 56) fc -= 56;
        src = (size_t)batch * 3136 + fr * 56 + fc;
    } else {
        src = token;
    }
    const float* xr = x + src * CDIM;
    const int tid = threadIdx.x;
    float v0 = xr[tid], v1 = xr[tid + 128], v2 = xr[tid + 256];
    float s  = v0 + v1 + v2;
    float s2 = v0 * v0 + v1 * v1 + v2 * v2;
    #pragma unroll
    for (int o2 = 16; o2 > 0; o2 >>= 1) {
        s  += __shfl_xor_sync(FULLMASK, s,  o2);
        s2 += __shfl_xor_sync(FULLMASK, s2, o2);
    }
    int w = tid >> 5;
    if ((tid & 31) == 0) { sa[w] = s; sb[w] = s2; }
    __syncthreads();
    s  = sa[0] + sa[1] + sa[2] + sa[3];
    s2 = sb[0] + sb[1] + sb[2] + sb[3];
    const float mean = s * (1.0f / 384.0f);
    const float var  = s2 * (1.0f / 384.0f) - mean * mean;
    const float rstd = rsqrtf(var + 1e-5f);
    size_t ob = (size_t)token * CDIM;
    o[ob + tid]       = __float2half_rn((v0 - mean) * rstd * g[tid]       + bta[tid]);
    o[ob + tid + 128] = __float2half_rn((v1 - mean) * rstd * g[tid + 128] + bta[tid + 128]);
    o[ob + tid + 256] = __float2half_rn((v2 - mean) * rstd * g[tid + 256] + bta[tid + 256]);
}

// ---------------- windowed attention: one block per (window, head) ---------
// Chunk-local: b = 0..511; (b & 63) is invariant under the chunk offset.
__global__ __launch_bounds__(256)
void attn_kernel(const __half* __restrict__ qkv, const float* __restrict__ rpb,
                 const float* __restrict__ mask, __half* __restrict__ o)
{
    __shared__ float qs[49 * 36];   // 144B row stride
    __shared__ float ks[49 * 36];
    __shared__ float vs[49 * 32];
    __shared__ float sc[49 * 49];

    const int b = blockIdx.y;
    const int h = blockIdx.x;
    const int tid = threadIdx.x;
    const int warp = tid >> 5, lane = tid & 31;

    const __half* base = qkv + (size_t)b * 49 * N3 + h * HD;
    for (int idx = tid; idx < 49 * 16; idx += 256) {
        int n = idx >> 4, d2 = idx & 15;
        const __half2* row = (const __half2*)(base + (size_t)n * N3);
        float2 q2 = __half22float2(row[d2]);
        float2 k2 = __half22float2(row[192 + d2]);   // +384 halves
        float2 v2 = __half22float2(row[384 + d2]);   // +768 halves
        qs[n * 36 + 2 * d2] = q2.x; qs[n * 36 + 2 * d2 + 1] = q2.y;
        ks[n * 36 + 2 * d2] = k2.x; ks[n * 36 + 2 * d2 + 1] = k2.y;
        vs[n * 32 + 2 * d2] = v2.x; vs[n * 32 + 2 * d2 + 1] = v2.y;
    }
    __syncthreads();

    const float scale = 0.17677669529663687f;  // 1/sqrt(32)
    const float* mrow = mask + (size_t)(b & 63) * 2401;

    // ---- scores: warp w handles rows {w, w+8, ...}; lane covers m=lane,(lane+32)
    for (int n = warp; n < 49; n += 8) {
        float4 q[8];
        #pragma unroll
        for (int s = 0; s < 8; s++) q[s] = *(const float4*)&qs[n * 36 + s * 4];
        const int r1 = n / 7, c1 = n - r1 * 7;

        float s0 = 0.0f;
        #pragma unroll
        for (int s = 0; s < 8; s++) {
            float4 k0 = *(const float4*)&ks[lane * 36 + s * 4];
            s0 += q[s].x * k0.x + q[s].y * k0.y + q[s].z * k0.z + q[s].w * k0.w;
        }
        float s1 = 0.0f;
        if (lane < 17) {
            #pragma unroll
            for (int s = 0; s < 8; s++) {
                float4 k1 = *(const float4*)&ks[(lane + 32) * 36 + s * 4];
                s1 += q[s].x * k1.x + q[s].y * k1.y + q[s].z * k1.z + q[s].w * k1.w;
            }
        }
        {
            const int m = lane;
            int r2 = m / 7, c2 = m - r2 * 7;
            int ridx = (r1 - r2 + 6) * 13 + (c1 - c2 + 6);
            sc[n * 49 + m] = s0 * scale + rpb[ridx * NHEAD + h] + mrow[n * 49 + m];
        }
        if (lane < 17) {
            const int m = lane + 32;
            int r2 = m / 7, c2 = m - r2 * 7;
            int ridx = (r1 - r2 + 6) * 13 + (c1 - c2 + 6);
            sc[n * 49 + m] = s1 * scale + rpb[ridx * NHEAD + h] + mrow[n * 49 + m];
        }
    }
    __syncthreads();

    // ---- softmax: warp per row
    for (int row = warp; row < 49; row += 8) {
        float* sr = sc + row * 49;
        float v0 = sr[lane];
        float v1 = (lane + 32 < 49) ? sr[lane + 32] : -1e30f;
        float mx = fmaxf(v0, v1);
        #pragma unroll
        for (int o2 = 16; o2 > 0; o2 >>= 1) mx = fmaxf(mx, __shfl_xor_sync(FULLMASK, mx, o2));
        float e0 = __expf(v0 - mx);
        float e1 = (lane + 32 < 49) ? __expf(v1 - mx) : 0.0f;
        float sm = e0 + e1;
        #pragma unroll
        for (int o2 = 16; o2 > 0; o2 >>= 1) sm += __shfl_xor_sync(FULLMASK, sm, o2);
        float inv = 1.0f / sm;
        sr[lane] = e0 * inv;
        if (lane + 32 < 49) sr[lane + 32] = e1 * inv;
    }
    __syncthreads();

    // ---- PV: warp handles 2 rows at a time; lane = (row-half, d-pair)
    const int half_ = lane >> 4, d2 = lane & 15;
    for (int np = warp; np < 25; np += 8) {
        const int n = np * 2 + half_;
        if (n < 49) {
            const float* pr = sc + n * 49;
            float ax = 0.0f, ay = 0.0f;
            #pragma unroll 7
            for (int m = 0; m < 49; m++) {
                float p = pr[m];
                float2 vv = *(const float2*)&vs[m * 32 + 2 * d2];
                ax += p * vv.x; ay += p * vv.y;
            }
            __half2 hp;
            hp.x = __float2half_rn(ax); hp.y = __float2half_rn(ay);
            *(__half2*)(o + (size_t)(b * 49 + n) * CDIM + h * HD + 2 * d2) = hp;
        }
    }
}

// ---------------- HMMA GEMM: C = A(M,K) @ Bt(N,K)^T + bias, fused epi ------
// fp16 single-term. 4 warps (2x2), warp tile 64x64, 2-stage cp.async,
// 2 CTAs/SM. Chunk-local rows; EPI2's window-reverse uses chunk-local batch.
// EPI: 0 = bias -> fp16 (qkv)     1 = bias + GELU -> fp16 (fc1)
//      2 = bias + window-reverse scatter + residual -> fp32 (proj)
//      3 = bias + residual -> fp32 (fc2 -> d_out)
template<int EPI>
__global__ __launch_bounds__(128, 2)
void gemm_tc(const __half* __restrict__ A, const __half* __restrict__ B,
             const float* __restrict__ bias, const float* __restrict__ res,
             float* __restrict__ outf, __half* __restrict__ oh,
             int N, int K)
{
    extern __shared__ __align__(128) char smem[];
    const uint32_t sbase = smem_u32(smem);
    const int tid  = threadIdx.x;
    const int wid  = tid >> 5, lane = tid & 31;
    const int warp_m = wid & 1, warp_n = wid >> 1;
    const int m0 = blockIdx.y << 7, n0 = blockIdx.x << 7;
    const int nc = K >> 6;

    float acc[4][8][4];
    #pragma unroll
    for (int i = 0; i < 4; i++)
        #pragma unroll
        for (int j = 0; j < 8; j++)
            #pragma unroll
            for (int e = 0; e < 4; e++) acc[i][j][e] = 0.0f;

    auto load_chunk = [&](int k0, int st) {
        const uint32_t so = sbase + st * STAGEB;
        #pragma unroll
        for (int t = 0; t < 2; t++) {
            const __half* gb = t ? B : A;
            const int rb = t ? n0 : m0;
            #pragma unroll
            for (int it = 0; it < 8; it++) {
                int slot = (it << 7) + tid;           // 0..1023
                int row = slot >> 3, seg = slot & 7;
                cp16(so + t * TBYTES + row * ROWB + (seg << 4),
                     gb + (size_t)(rb + row) * K + k0 + (seg << 3));
            }
        }
        CP_COMMIT();
    };

    load_chunk(0, 0);

    const int arow = (lane & 7) + (lane & 8);
    const int acol = ((lane >> 4) << 3);
    const int brow = (lane & 7) + ((lane >> 1) & 8);
    const int bcol = (lane & 8);

    for (int c = 0; c < nc; c++) {
        if (c + 1 < nc) { load_chunk((c + 1) << 6, (c + 1) & 1); CP_WAIT(1); }
        else            { CP_WAIT(0); }
        __syncthreads();

        const uint32_t sA = sbase + (c & 1) * STAGEB;
        const uint32_t sB = sA + TBYTES;

        #pragma unroll
        for (int ks = 0; ks < 4; ks++) {
            const int kb = ks << 4;
            uint32_t af[4][4];
            #pragma unroll
            for (int mf = 0; mf < 4; mf++)
                ldm_x4(af[mf], sA + (warp_m * 64 + mf * 16 + arow) * ROWB + (kb + acol) * 2);
            uint32_t bf[4][4];
            #pragma unroll
            for (int nt = 0; nt < 4; nt++)
                ldm_x4(bf[nt], sB + (warp_n * 64 + nt * 16 + brow) * ROWB + (kb + bcol) * 2);
            #pragma unroll
            for (int mf = 0; mf < 4; mf++)
                #pragma unroll
                for (int nf = 0; nf < 8; nf++) {
                    const int nt = nf >> 1, bs = (nf & 1) << 1;
                    mma_f16(acc[mf][nf], af[mf], bf[nt][bs], bf[nt][bs + 1]);
                }
        }
        __syncthreads();
    }

    // ---------------- epilogue ---------------------------------------------
    #pragma unroll
    for (int mf = 0; mf < 4; mf++) {
        #pragma unroll
        for (int hh = 0; hh < 2; hh++) {
            const int gm = m0 + warp_m * 64 + mf * 16 + (lane >> 2) + hh * 8;
            size_t obase;
            if (EPI == 2) {
                int bwin  = gm / 49;          // chunk-local window 0..511
                int n     = gm - bwin * 49;
                int batch = bwin >> 6;        // chunk-local batch 0..7
                int widx  = bwin & 63;
                int wh = widx >> 3, ww = widx & 7;
                int r = n / 7, cc = n - r * 7;
                int fr = wh * 7 + r + 3;  if (fr >= 56) fr -= 56;
                int fc = ww * 7 + cc + 3; if (fc >= 56) fc -= 56;
                obase = ((size_t)batch * 3136 + fr * 56 + fc) * CDIM;
            } else {
                obase = (size_t)gm * N;
            }
            #pragma unroll
            for (int nf = 0; nf < 8; nf++) {
                const int gn = n0 + warp_n * 64 + nf * 8 + ((lane & 3) << 1);
                float v0 = acc[mf][nf][hh * 2 + 0];
                float v1 = acc[mf][nf][hh * 2 + 1];
                float2 bv = *(const float2*)(bias + gn);
                v0 += bv.x; v1 += bv.y;
                if (EPI == 0 || EPI == 1) {
                    if (EPI == 1) {
                        v0 = 0.5f * v0 * (1.0f + erff(v0 * 0.70710678118654752f));
                        v1 = 0.5f * v1 * (1.0f + erff(v1 * 0.70710678118654752f));
                    }
                    __half2 hp;
                    hp.x = __float2half_rn(v0); hp.y = __float2half_rn(v1);
                    *(__half2*)(oh + obase + gn) = hp;
                } else {
                    float2 rv = *(const float2*)(res + obase + gn);
                    v0 += rv.x; v1 += rv.y;
                    float2 o; o.x = v0; o.y = v1;
                    *(float2*)(outf + obase + gn) = o;
                }
            }
        }
    }
}

// ---------------------------------------------------------------------------
extern "C" void kernel_launch(void* const* d_in, const int* in_sizes, int n_in,
                              void* d_out, int out_size)
{
    const float* x     = (const float*)d_in[0];
    const float* amask = (const float*)d_in[1];
    const float* n1g   = (const float*)d_in[2];
    const float* n1b   = (const float*)d_in[3];
    const float* qkvW  = (const float*)d_in[4];
    const float* qkvB  = (const float*)d_in[5];
    const float* rpb   = (const float*)d_in[6];
    const float* projW = (const float*)d_in[7];
    const float* projB = (const float*)d_in[8];
    const float* n2g   = (const float*)d_in[9];
    const float* n2b   = (const float*)d_in[10];
    const float* fc1W  = (const float*)d_in[11];
    const float* fc1B  = (const float*)d_in[12];
    const float* fc2W  = (const float*)d_in[13];
    const float* fc2B  = (const float*)d_in[14];
    float* out = (float*)d_out;

    float *x1;
    __half *qkv16, *a16, *h16, *wq, *wp, *w1, *w2;
    cudaGetSymbolAddress((void**)&qkv16, g_qkv16);
    cudaGetSymbolAddress((void**)&x1,  g_x1);
    cudaGetSymbolAddress((void**)&a16, g_a);
    cudaGetSymbolAddress((void**)&h16, g_h);
    cudaGetSymbolAddress((void**)&wq,  g_wqkv);
    cudaGetSymbolAddress((void**)&wp,  g_wprj);
    cudaGetSymbolAddress((void**)&w1,  g_wfc1);
    cudaGetSymbolAddress((void**)&w2,  g_wfc2);

    cudaFuncSetAttribute(gemm_tc<0>, cudaFuncAttributeMaxDynamicSharedMemorySize, SMEM_TOTAL);
    cudaFuncSetAttribute(gemm_tc<1>, cudaFuncAttributeMaxDynamicSharedMemorySize, SMEM_TOTAL);
    cudaFuncSetAttribute(gemm_tc<2>, cudaFuncAttributeMaxDynamicSharedMemorySize, SMEM_TOTAL);
    cudaFuncSetAttribute(gemm_tc<3>, cudaFuncAttributeMaxDynamicSharedMemorySize, SMEM_TOTAL);

    // 0. weight transpose to fp16 (tiny)
    wT<<<(N3  * CDIM + 255) / 256, 256>>>(qkvW, wq, CDIM, N3);
    wT<<<(CDIM* CDIM + 255) / 256, 256>>>(projW, wp, CDIM, CDIM);
    wT<<<(HIDD* CDIM + 255) / 256, 256>>>(fc1W, w1, CDIM, HIDD);
    wT<<<(CDIM* HIDD + 255) / 256, 256>>>(fc2W, w2, HIDD, CDIM);

    // Process 4 batch-chunks (8 images each); all intermediates chunk-local.
    for (int ch = 0; ch < NCHUNK; ch++) {
        const float* xc  = x   + (size_t)ch * CHTOK * CDIM;
        float*       oc  = out + (size_t)ch * CHTOK * CDIM;

        // 1. LN1 + roll + window partition -> fp16 (chunk-local rows)
        ln_kernel<true><<<CHTOK, 128>>>(xc, n1g, n1b, a16);
        // 2. qkv GEMM (N=1152, K=384) -> fp16
        gemm_tc<0><<<dim3(9, 196), 128, SMEM_TOTAL>>>(a16, wq, qkvB, nullptr,
                                                      nullptr, qkv16, N3, CDIM);
        // 3. windowed attention -> fp16 (reuse a16)
        attn_kernel<<<dim3(NHEAD, CHWIN), 256>>>(qkv16, rpb, amask, a16);
        // 4. proj GEMM + window-reverse scatter + residual(x chunk) -> x1
        gemm_tc<2><<<dim3(3, 196), 128, SMEM_TOTAL>>>(a16, wp, projB, xc,
                                                      x1, nullptr, CDIM, CDIM);
        // 5. LN2 -> fp16
        ln_kernel<false><<<CHTOK, 128>>>(x1, n2g, n2b, a16);
        // 6. fc1 GEMM + GELU -> fp16 hidden
        gemm_tc<1><<<dim3(12, 196), 128, SMEM_TOTAL>>>(a16, w1, fc1B, nullptr,
                                                       nullptr, h16, HIDD, CDIM);
        // 7. fc2 GEMM + residual(x1) -> d_out chunk
        gemm_tc<3><<<dim3(3, 196), 128, SMEM_TOTAL>>>(h16, w2, fc2B, x1,
                                                      oc, nullptr, CDIM, HIDD);
    }
}

// round 17
// speedup vs baseline: 1.0972x; 1.0972x over previous
#include <cuda_runtime.h>
#include <cuda_fp16.h>
#include <math.h>
#include <stdint.h>

// ---------------------------------------------------------------------------
// SwinBlock, GEMMs on HMMA mma.sync m16n8k16 fp16 (fp32 acc).
// R16: revert R15 chunking (regressed). LN -> warp-per-token (no smem/bar),
// 4 weight-transpose launches merged into 1.
// Shapes fixed: B=32, H=W=56, C=384, NH=12, hd=32, WS=7, SHIFT=3, HID=1536
// ---------------------------------------------------------------------------

#define NTOK   100352          // 2048 windows * 49 tokens
#define CDIM   384
#define NHEAD  12
#define HD     32
#define N3     1152
#define HIDD   1536
#define FULLMASK 0xffffffffu

// GEMM tiling: CTA 128x128, BK=64, 2-stage cp.async pipeline, 128 threads
#define BK       64
#define ROWB     144                       // 64 fp16 = 128B, padded to 144B
#define TBYTES   (128 * ROWB)              // 18432 per tensor tile
#define STAGEB   (2 * TBYTES)              // A tile + B tile = 36864
#define NSTAGE   2
#define SMEM_TOTAL (NSTAGE * STAGEB)       // 73728 B dynamic smem

// ---------------- scratch (static device globals; no allocation) -----------
__device__ __half  g_qkv16[(size_t)NTOK * N3];  // fp16 qkv
__device__ float   g_x1 [(size_t)NTOK * CDIM];  // residual stream
__device__ __half  g_a  [(size_t)NTOK * CDIM];  // fp16 activations (reused)
__device__ __half  g_h  [(size_t)NTOK * HIDD];  // fp16 MLP hidden
// transposed fp16 weights: Wt[N][K]
__device__ __half  g_wqkv[N3  * CDIM];
__device__ __half  g_wprj[CDIM* CDIM];
__device__ __half  g_wfc1[HIDD* CDIM];
__device__ __half  g_wfc2[CDIM* HIDD];

// ---------------- PTX helpers ----------------------------------------------
__device__ __forceinline__ uint32_t smem_u32(const void* p) {
    uint32_t a;
    asm("{ .reg .u64 t; cvta.to.shared.u64 t, %1; cvt.u32.u64 %0, t; }"
        : "=r"(a) : "l"(p));
    return a;
}
__device__ __forceinline__ void ldm_x4(uint32_t* r, uint32_t a) {
    asm volatile("ldmatrix.sync.aligned.m8n8.x4.shared.b16 {%0,%1,%2,%3}, [%4];"
                 : "=r"(r[0]), "=r"(r[1]), "=r"(r[2]), "=r"(r[3]) : "r"(a));
}
__device__ __forceinline__ void mma_f16(float* c, const uint32_t* a,
                                        uint32_t b0, uint32_t b1) {
    asm volatile("mma.sync.aligned.m16n8k16.row.col.f32.f16.f16.f32 "
                 "{%0,%1,%2,%3}, {%4,%5,%6,%7}, {%8,%9}, {%0,%1,%2,%3};"
                 : "+f"(c[0]), "+f"(c[1]), "+f"(c[2]), "+f"(c[3])
                 : "r"(a[0]), "r"(a[1]), "r"(a[2]), "r"(a[3]), "r"(b0), "r"(b1));
}
__device__ __forceinline__ void cp16(uint32_t sa, const void* ga) {
    asm volatile("cp.async.cg.shared.global [%0], [%1], 16;" :: "r"(sa), "l"(ga));
}
#define CP_COMMIT()  asm volatile("cp.async.commit_group;")
#define CP_WAIT(n)   asm volatile("cp.async.wait_group %0;" :: "n"(n))

// ---------------- merged weight transpose: W[K][N] -> Wt[N][K] fp16 ---------
#define WQ_E (N3  * CDIM)
#define WP_E (CDIM* CDIM)
#define W1_E (HIDD* CDIM)
#define W2_E (CDIM* HIDD)
#define WT_TOTAL (WQ_E + WP_E + W1_E + W2_E)
__global__ void wT_all(const float* __restrict__ qkvW, const float* __restrict__ projW,
                       const float* __restrict__ fc1W, const float* __restrict__ fc2W,
                       __half* __restrict__ wq, __half* __restrict__ wp,
                       __half* __restrict__ w1, __half* __restrict__ w2)
{
    int idx = blockIdx.x * 256 + threadIdx.x;
    if (idx < WQ_E) {
        int n = idx / CDIM, k = idx - n * CDIM;
        wq[idx] = __float2half_rn(qkvW[(size_t)k * N3 + n]);
    } else if (idx < WQ_E + WP_E) {
        int i = idx - WQ_E;
        int n = i / CDIM, k = i - n * CDIM;
        wp[i] = __float2half_rn(projW[(size_t)k * CDIM + n]);
    } else if (idx < WQ_E + WP_E + W1_E) {
        int i = idx - WQ_E - WP_E;
        int n = i / CDIM, k = i - n * CDIM;
        w1[i] = __float2half_rn(fc1W[(size_t)k * HIDD + n]);
    } else if (idx < WT_TOTAL) {
        int i = idx - WQ_E - WP_E - W1_E;
        int n = i / HIDD, k = i - n * HIDD;
        w2[i] = __float2half_rn(fc2W[(size_t)k * CDIM + n]);
    }
}

// ---------------- LayerNorm: warp-per-token, no smem, no block barrier -----
// 256 threads = 8 tokens per block; float4 loads, shfl reduce, uint2 stores.
template<bool WINDOW>
__global__ __launch_bounds__(256)
void ln_kernel(const float* __restrict__ x, const float* __restrict__ g,
               const float* __restrict__ bta, __half* __restrict__ o)
{
    const int token = blockIdx.x * 8 + (threadIdx.x >> 5);
    const int lane  = threadIdx.x & 31;
    size_t src;
    if (WINDOW) {
        int bwin  = token / 49;
        int n     = token - bwin * 49;
        int batch = bwin >> 6;
        int widx  = bwin & 63;
        int wh = widx >> 3, ww = widx & 7;
        int r = n / 7, c = n - r * 7;
        int fr = wh * 7 + r + 3; if (fr >= 56) fr -= 56;
        int fc = ww * 7 + c + 3; if (fc >= 56) fc -= 56;
        src = (size_t)batch * 3136 + fr * 56 + fc;
    } else {
        src = token;
    }
    const float4* xr = (const float4*)(x + src * CDIM);
    float4 v[3];
    #pragma unroll
    for (int i = 0; i < 3; i++) v[i] = xr[lane + (i << 5)];
    float s = 0.0f, s2 = 0.0f;
    #pragma unroll
    for (int i = 0; i < 3; i++) {
        s  += v[i].x + v[i].y + v[i].z + v[i].w;
        s2 += v[i].x * v[i].x + v[i].y * v[i].y + v[i].z * v[i].z + v[i].w * v[i].w;
    }
    #pragma unroll
    for (int o2 = 16; o2 > 0; o2 >>= 1) {
        s  += __shfl_xor_sync(FULLMASK, s,  o2);
        s2 += __shfl_xor_sync(FULLMASK, s2, o2);
    }
    const float mean = s * (1.0f / 384.0f);
    const float var  = s2 * (1.0f / 384.0f) - mean * mean;
    const float rstd = rsqrtf(var + 1e-5f);
    const float4* gg = (const float4*)g;
    const float4* bb = (const float4*)bta;
    uint2* orow = (uint2*)(o + (size_t)token * CDIM);
    #pragma unroll
    for (int i = 0; i < 3; i++) {
        float4 gv = gg[lane + (i << 5)], bv = bb[lane + (i << 5)];
        __half2 h0 = __floats2half2_rn((v[i].x - mean) * rstd * gv.x + bv.x,
                                       (v[i].y - mean) * rstd * gv.y + bv.y);
        __half2 h1 = __floats2half2_rn((v[i].z - mean) * rstd * gv.z + bv.z,
                                       (v[i].w - mean) * rstd * gv.w + bv.w);
        uint2 pk;
        pk.x = *(unsigned*)&h0; pk.y = *(unsigned*)&h1;
        orow[lane + (i << 5)] = pk;
    }
}

// ---------------- windowed attention: one block per (window, head) ---------
__global__ __launch_bounds__(256)
void attn_kernel(const __half* __restrict__ qkv, const float* __restrict__ rpb,
                 const float* __restrict__ mask, __half* __restrict__ o)
{
    __shared__ float qs[49 * 36];   // 144B row stride
    __shared__ float ks[49 * 36];
    __shared__ float vs[49 * 32];
    __shared__ float sc[49 * 49];

    const int b = blockIdx.y;
    const int h = blockIdx.x;
    const int tid = threadIdx.x;
    const int warp = tid >> 5, lane = tid & 31;

    const __half* base = qkv + (size_t)b * 49 * N3 + h * HD;
    for (int idx = tid; idx < 49 * 16; idx += 256) {
        int n = idx >> 4, d2 = idx & 15;
        const __half2* row = (const __half2*)(base + (size_t)n * N3);
        float2 q2 = __half22float2(row[d2]);
        float2 k2 = __half22float2(row[192 + d2]);   // +384 halves
        float2 v2 = __half22float2(row[384 + d2]);   // +768 halves
        qs[n * 36 + 2 * d2] = q2.x; qs[n * 36 + 2 * d2 + 1] = q2.y;
        ks[n * 36 + 2 * d2] = k2.x; ks[n * 36 + 2 * d2 + 1] = k2.y;
        vs[n * 32 + 2 * d2] = v2.x; vs[n * 32 + 2 * d2 + 1] = v2.y;
    }
    __syncthreads();

    const float scale = 0.17677669529663687f;  // 1/sqrt(32)
    const float* mrow = mask + (size_t)(b & 63) * 2401;

    // ---- scores: warp w handles rows {w, w+8, ...}; lane covers m=lane,(lane+32)
    for (int n = warp; n < 49; n += 8) {
        float4 q[8];
        #pragma unroll
        for (int s = 0; s < 8; s++) q[s] = *(const float4*)&qs[n * 36 + s * 4];
        const int r1 = n / 7, c1 = n - r1 * 7;

        float s0 = 0.0f;
        #pragma unroll
        for (int s = 0; s < 8; s++) {
            float4 k0 = *(const float4*)&ks[lane * 36 + s * 4];
            s0 += q[s].x * k0.x + q[s].y * k0.y + q[s].z * k0.z + q[s].w * k0.w;
        }
        float s1 = 0.0f;
        if (lane < 17) {
            #pragma unroll
            for (int s = 0; s < 8; s++) {
                float4 k1 = *(const float4*)&ks[(lane + 32) * 36 + s * 4];
                s1 += q[s].x * k1.x + q[s].y * k1.y + q[s].z * k1.z + q[s].w * k1.w;
            }
        }
        {
            const int m = lane;
            int r2 = m / 7, c2 = m - r2 * 7;
            int ridx = (r1 - r2 + 6) * 13 + (c1 - c2 + 6);
            sc[n * 49 + m] = s0 * scale + rpb[ridx * NHEAD + h] + mrow[n * 49 + m];
        }
        if (lane < 17) {
            const int m = lane + 32;
            int r2 = m / 7, c2 = m - r2 * 7;
            int ridx = (r1 - r2 + 6) * 13 + (c1 - c2 + 6);
            sc[n * 49 + m] = s1 * scale + rpb[ridx * NHEAD + h] + mrow[n * 49 + m];
        }
    }
    __syncthreads();

    // ---- softmax: warp per row
    for (int row = warp; row < 49; row += 8) {
        float* sr = sc + row * 49;
        float v0 = sr[lane];
        float v1 = (lane + 32 < 49) ? sr[lane + 32] : -1e30f;
        float mx = fmaxf(v0, v1);
        #pragma unroll
        for (int o2 = 16; o2 > 0; o2 >>= 1) mx = fmaxf(mx, __shfl_xor_sync(FULLMASK, mx, o2));
        float e0 = __expf(v0 - mx);
        float e1 = (lane + 32 < 49) ? __expf(v1 - mx) : 0.0f;
        float sm = e0 + e1;
        #pragma unroll
        for (int o2 = 16; o2 > 0; o2 >>= 1) sm += __shfl_xor_sync(FULLMASK, sm, o2);
        float inv = 1.0f / sm;
        sr[lane] = e0 * inv;
        if (lane + 32 < 49) sr[lane + 32] = e1 * inv;
    }
    __syncthreads();

    // ---- PV: warp handles 2 rows at a time; lane = (row-half, d-pair)
    const int half_ = lane >> 4, d2 = lane & 15;
    for (int np = warp; np < 25; np += 8) {
        const int n = np * 2 + half_;
        if (n < 49) {
            const float* pr = sc + n * 49;
            float ax = 0.0f, ay = 0.0f;
            #pragma unroll 7
            for (int m = 0; m < 49; m++) {
                float p = pr[m];
                float2 vv = *(const float2*)&vs[m * 32 + 2 * d2];
                ax += p * vv.x; ay += p * vv.y;
            }
            __half2 hp;
            hp.x = __float2half_rn(ax); hp.y = __float2half_rn(ay);
            *(__half2*)(o + (size_t)(b * 49 + n) * CDIM + h * HD + 2 * d2) = hp;
        }
    }
}

// ---------------- HMMA GEMM: C = A(M,K) @ Bt(N,K)^T + bias, fused epi ------
// fp16 single-term. 4 warps (2x2), warp tile 64x64, 2-stage cp.async,
// 2 CTAs/SM.
// EPI: 0 = bias -> fp16 (qkv)     1 = bias + GELU -> fp16 (fc1)
//      2 = bias + window-reverse scatter + residual -> fp32 (proj)
//      3 = bias + residual -> fp32 (fc2 -> d_out)
template<int EPI>
__global__ __launch_bounds__(128, 2)
void gemm_tc(const __half* __restrict__ A, const __half* __restrict__ B,
             const float* __restrict__ bias, const float* __restrict__ res,
             float* __restrict__ outf, __half* __restrict__ oh,
             int N, int K)
{
    extern __shared__ __align__(128) char smem[];
    const uint32_t sbase = smem_u32(smem);
    const int tid  = threadIdx.x;
    const int wid  = tid >> 5, lane = tid & 31;
    const int warp_m = wid & 1, warp_n = wid >> 1;
    const int m0 = blockIdx.y << 7, n0 = blockIdx.x << 7;
    const int nc = K >> 6;

    float acc[4][8][4];
    #pragma unroll
    for (int i = 0; i < 4; i++)
        #pragma unroll
        for (int j = 0; j < 8; j++)
            #pragma unroll
            for (int e = 0; e < 4; e++) acc[i][j][e] = 0.0f;

    auto load_chunk = [&](int k0, int st) {
        const uint32_t so = sbase + st * STAGEB;
        #pragma unroll
        for (int t = 0; t < 2; t++) {
            const __half* gb = t ? B : A;
            const int rb = t ? n0 : m0;
            #pragma unroll
            for (int it = 0; it < 8; it++) {
                int slot = (it << 7) + tid;           // 0..1023
                int row = slot >> 3, seg = slot & 7;
                cp16(so + t * TBYTES + row * ROWB + (seg << 4),
                     gb + (size_t)(rb + row) * K + k0 + (seg << 3));
            }
        }
        CP_COMMIT();
    };

    load_chunk(0, 0);

    const int arow = (lane & 7) + (lane & 8);
    const int acol = ((lane >> 4) << 3);
    const int brow = (lane & 7) + ((lane >> 1) & 8);
    const int bcol = (lane & 8);

    for (int c = 0; c < nc; c++) {
        if (c + 1 < nc) { load_chunk((c + 1) << 6, (c + 1) & 1); CP_WAIT(1); }
        else            { CP_WAIT(0); }
        __syncthreads();

        const uint32_t sA = sbase + (c & 1) * STAGEB;
        const uint32_t sB = sA + TBYTES;

        #pragma unroll
        for (int ks = 0; ks < 4; ks++) {
            const int kb = ks << 4;
            uint32_t af[4][4];
            #pragma unroll
            for (int mf = 0; mf < 4; mf++)
                ldm_x4(af[mf], sA + (warp_m * 64 + mf * 16 + arow) * ROWB + (kb + acol) * 2);
            uint32_t bf[4][4];
            #pragma unroll
            for (int nt = 0; nt < 4; nt++)
                ldm_x4(bf[nt], sB + (warp_n * 64 + nt * 16 + brow) * ROWB + (kb + bcol) * 2);
            #pragma unroll
            for (int mf = 0; mf < 4; mf++)
                #pragma unroll
                for (int nf = 0; nf < 8; nf++) {
                    const int nt = nf >> 1, bs = (nf & 1) << 1;
                    mma_f16(acc[mf][nf], af[mf], bf[nt][bs], bf[nt][bs + 1]);
                }
        }
        __syncthreads();
    }

    // ---------------- epilogue ---------------------------------------------
    #pragma unroll
    for (int mf = 0; mf < 4; mf++) {
        #pragma unroll
        for (int hh = 0; hh < 2; hh++) {
            const int gm = m0 + warp_m * 64 + mf * 16 + (lane >> 2) + hh * 8;
            size_t obase;
            if (EPI == 2) {
                int bwin  = gm / 49;
                int n     = gm - bwin * 49;
                int batch = bwin >> 6;
                int widx  = bwin & 63;
                int wh = widx >> 3, ww = widx & 7;
                int r = n / 7, cc = n - r * 7;
                int fr = wh * 7 + r + 3;  if (fr >= 56) fr -= 56;
                int fc = ww * 7 + cc + 3; if (fc >= 56) fc -= 56;
                obase = ((size_t)batch * 3136 + fr * 56 + fc) * CDIM;
            } else {
                obase = (size_t)gm * N;
            }
            #pragma unroll
            for (int nf = 0; nf < 8; nf++) {
                const int gn = n0 + warp_n * 64 + nf * 8 + ((lane & 3) << 1);
                float v0 = acc[mf][nf][hh * 2 + 0];
                float v1 = acc[mf][nf][hh * 2 + 1];
                float2 bv = *(const float2*)(bias + gn);
                v0 += bv.x; v1 += bv.y;
                if (EPI == 0 || EPI == 1) {
                    if (EPI == 1) {
                        v0 = 0.5f * v0 * (1.0f + erff(v0 * 0.70710678118654752f));
                        v1 = 0.5f * v1 * (1.0f + erff(v1 * 0.70710678118654752f));
                    }
                    __half2 hp;
                    hp.x = __float2half_rn(v0); hp.y = __float2half_rn(v1);
                    *(__half2*)(oh + obase + gn) = hp;
                } else {
                    float2 rv = *(const float2*)(res + obase + gn);
                    v0 += rv.x; v1 += rv.y;
                    float2 o; o.x = v0; o.y = v1;
                    *(float2*)(outf + obase + gn) = o;
                }
            }
        }
    }
}

// ---------------------------------------------------------------------------
extern "C" void kernel_launch(void* const* d_in, const int* in_sizes, int n_in,
                              void* d_out, int out_size)
{
    const float* x     = (const float*)d_in[0];
    const float* amask = (const float*)d_in[1];
    const float* n1g   = (const float*)d_in[2];
    const float* n1b   = (const float*)d_in[3];
    const float* qkvW  = (const float*)d_in[4];
    const float* qkvB  = (const float*)d_in[5];
    const float* rpb   = (const float*)d_in[6];
    const float* projW = (const float*)d_in[7];
    const float* projB = (const float*)d_in[8];
    const float* n2g   = (const float*)d_in[9];
    const float* n2b   = (const float*)d_in[10];
    const float* fc1W  = (const float*)d_in[11];
    const float* fc1B  = (const float*)d_in[12];
    const float* fc2W  = (const float*)d_in[13];
    const float* fc2B  = (const float*)d_in[14];
    float* out = (float*)d_out;

    float *x1;
    __half *qkv16, *a16, *h16, *wq, *wp, *w1, *w2;
    cudaGetSymbolAddress((void**)&qkv16, g_qkv16);
    cudaGetSymbolAddress((void**)&x1,  g_x1);
    cudaGetSymbolAddress((void**)&a16, g_a);
    cudaGetSymbolAddress((void**)&h16, g_h);
    cudaGetSymbolAddress((void**)&wq,  g_wqkv);
    cudaGetSymbolAddress((void**)&wp,  g_wprj);
    cudaGetSymbolAddress((void**)&w1,  g_wfc1);
    cudaGetSymbolAddress((void**)&w2,  g_wfc2);

    cudaFuncSetAttribute(gemm_tc<0>, cudaFuncAttributeMaxDynamicSharedMemorySize, SMEM_TOTAL);
    cudaFuncSetAttribute(gemm_tc<1>, cudaFuncAttributeMaxDynamicSharedMemorySize, SMEM_TOTAL);
    cudaFuncSetAttribute(gemm_tc<2>, cudaFuncAttributeMaxDynamicSharedMemorySize, SMEM_TOTAL);
    cudaFuncSetAttribute(gemm_tc<3>, cudaFuncAttributeMaxDynamicSharedMemorySize, SMEM_TOTAL);

    // 0. merged weight transpose to fp16 (1 launch)
    wT_all<<<(WT_TOTAL + 255) / 256, 256>>>(qkvW, projW, fc1W, fc2W, wq, wp, w1, w2);

    // 1. LN1 + roll + window partition -> fp16 (warp per token)
    ln_kernel<true><<<NTOK / 8, 256>>>(x, n1g, n1b, a16);
    // 2. qkv GEMM (N=1152, K=384) -> fp16
    gemm_tc<0><<<dim3(9, 784), 128, SMEM_TOTAL>>>(a16, wq, qkvB, nullptr, nullptr, qkv16, N3, CDIM);
    // 3. windowed attention -> fp16 (reuse a16)
    attn_kernel<<<dim3(NHEAD, 2048), 256>>>(qkv16, rpb, amask, a16);
    // 4. proj GEMM + window-reverse scatter + residual(x) -> x1
    gemm_tc<2><<<dim3(3, 784), 128, SMEM_TOTAL>>>(a16, wp, projB, x, x1, nullptr, CDIM, CDIM);
    // 5. LN2 -> fp16 (warp per token)
    ln_kernel<false><<<NTOK / 8, 256>>>(x1, n2g, n2b, a16);
    // 6. fc1 GEMM + GELU -> fp16 hidden
    gemm_tc<1><<<dim3(12, 784), 128, SMEM_TOTAL>>>(a16, w1, fc1B, nullptr, nullptr, h16, HIDD, CDIM);
    // 7. fc2 GEMM + residual(x1) -> d_out
    gemm_tc<3><<<dim3(3, 784), 128, SMEM_TOTAL>>>(h16, w2, fc2B, x1, out, nullptr, CDIM, HIDD);
}